// round 2
// baseline (speedup 1.0000x reference)
#include <cuda_runtime.h>

#define N_NODES 100000
#define N_EDGES 3200000
#define FEAT 128
#define HID 128
#define NCLS 64

// ---------------- scratch (device globals: no allocation allowed) ----------
__device__ int g_cnt_d[N_NODES];
__device__ int g_cnt_s[N_NODES];
__device__ int g_off_d[N_NODES + 1];
__device__ int g_off_s[N_NODES + 1];
__device__ int g_cur_d[N_NODES];
__device__ int g_cur_s[N_NODES];
__device__ int g_adj_d[N_EDGES];   // src ids bucketed by dst
__device__ int g_adj_s[N_EDGES];   // dst ids bucketed by src
__device__ float g_agg[(size_t)N_NODES * FEAT];   // mean-aggregated features
__device__ float g_h2[(size_t)N_NODES * NCLS];    // post-W_out hidden

// ---------------- 1. zero counters ----------------------------------------
__global__ void k_zero() {
    int i = blockIdx.x * blockDim.x + threadIdx.x;
    int stride = gridDim.x * blockDim.x;
    for (; i < N_NODES; i += stride) {
        g_cnt_d[i] = 0;
        g_cnt_s[i] = 0;
    }
}

// ---------------- 2. count degrees (edge_index is INT32) -------------------
__global__ void k_count(const int* __restrict__ ei) {
    int i = blockIdx.x * blockDim.x + threadIdx.x;
    if (i >= N_EDGES) return;
    int s = ei[i];
    int d = ei[N_EDGES + i];
    atomicAdd(&g_cnt_s[s], 1);
    atomicAdd(&g_cnt_d[d], 1);
}

// ---------------- 3. exclusive scan (single block, 1024 threads) -----------
__device__ void scan_one(const int* __restrict__ cnt, int* __restrict__ off,
                         int* __restrict__ cur) {
    __shared__ int wsum[32];
    __shared__ int carry_sh;
    int tid = threadIdx.x, lane = tid & 31, wid = tid >> 5;
    if (tid == 0) carry_sh = 0;
    __syncthreads();
    for (int base = 0; base < N_NODES; base += 1024) {
        int i = base + tid;
        int v = (i < N_NODES) ? cnt[i] : 0;
        int x = v;
#pragma unroll
        for (int o = 1; o < 32; o <<= 1) {
            int y = __shfl_up_sync(0xffffffffu, x, o);
            if (lane >= o) x += y;
        }
        if (lane == 31) wsum[wid] = x;
        __syncthreads();
        if (wid == 0) {
            int xx = wsum[lane];
#pragma unroll
            for (int o = 1; o < 32; o <<= 1) {
                int y = __shfl_up_sync(0xffffffffu, xx, o);
                if (lane >= o) xx += y;
            }
            wsum[lane] = xx;
        }
        __syncthreads();
        int incl = x + (wid > 0 ? wsum[wid - 1] : 0);
        int carry = carry_sh;
        if (i < N_NODES) {
            int e = carry + incl - v;
            off[i] = e;
            cur[i] = e;
        }
        __syncthreads();
        if (tid == 1023) carry_sh = carry + incl;  // chunk total
        __syncthreads();
    }
    if (threadIdx.x == 0) off[N_NODES] = carry_sh;
    __syncthreads();
}

__global__ void k_scan() {
    scan_one(g_cnt_d, g_off_d, g_cur_d);
    scan_one(g_cnt_s, g_off_s, g_cur_s);
}

// ---------------- 4. fill CSR buckets --------------------------------------
__global__ void k_fill(const int* __restrict__ ei) {
    int i = blockIdx.x * blockDim.x + threadIdx.x;
    if (i >= N_EDGES) return;
    int s = ei[i];
    int d = ei[N_EDGES + i];
    int p = atomicAdd(&g_cur_d[d], 1);
    g_adj_d[p] = s;
    int q = atomicAdd(&g_cur_s[s], 1);
    g_adj_s[q] = d;
}

// ---------------- 5. mean aggregation (warp per dst node, no atomics) ------
__global__ void k_aggregate(const float* __restrict__ feat) {
    int w = (blockIdx.x * blockDim.x + threadIdx.x) >> 5;
    if (w >= N_NODES) return;
    int lane = threadIdx.x & 31;
    int beg = g_off_d[w], end = g_off_d[w + 1];
    const float4* F = (const float4*)feat;
    float ax = 0.f, ay = 0.f, az = 0.f, aw = 0.f;
    int j = beg;
    for (; j + 4 <= end; j += 4) {
        int s0 = g_adj_d[j + 0];
        int s1 = g_adj_d[j + 1];
        int s2 = g_adj_d[j + 2];
        int s3 = g_adj_d[j + 3];
        float4 v0 = F[(size_t)s0 * 32 + lane];
        float4 v1 = F[(size_t)s1 * 32 + lane];
        float4 v2 = F[(size_t)s2 * 32 + lane];
        float4 v3 = F[(size_t)s3 * 32 + lane];
        ax += v0.x + v1.x + v2.x + v3.x;
        ay += v0.y + v1.y + v2.y + v3.y;
        az += v0.z + v1.z + v2.z + v3.z;
        aw += v0.w + v1.w + v2.w + v3.w;
    }
    for (; j < end; j++) {
        int s0 = g_adj_d[j];
        float4 v0 = F[(size_t)s0 * 32 + lane];
        ax += v0.x; ay += v0.y; az += v0.z; aw += v0.w;
    }
    float inv = (end > beg) ? 1.0f / (float)(end - beg) : 0.0f;
    float4 r;
    r.x = ax * inv; r.y = ay * inv; r.z = az * inv; r.w = aw * inv;
    ((float4*)g_agg)[(size_t)w * 32 + lane] = r;
}

// ---------------- 6. fused MLP: h=relu(agg@WlT + x@WrT)*m1*m2; h2=h@WoutT --
// Block: 256 threads, 64-node tile. Micro-tile: 8 nodes x 4 cols per thread.
__global__ __launch_bounds__(256) void k_mlp(
    const float* __restrict__ feat,
    const float* __restrict__ W_l, const float* __restrict__ W_r,
    const float* __restrict__ W_out,
    const float* __restrict__ mask1, const float* __restrict__ mask2) {
    __shared__ __align__(16) float As[64 * 128];   // node-input tile; reused as H
    __shared__ __align__(16) float Bs[16 * 132];   // transposed weight tile (padded)

    int tid = threadIdx.x;
    int c = tid & 31;    // col group: covers cols c*4..c*4+3 (stage1)
    int rg = tid >> 5;   // row group: nodes rg*8..rg*8+7
    int n0 = blockIdx.x * 64;

    float acc[8][4];
#pragma unroll
    for (int i = 0; i < 8; i++)
#pragma unroll
        for (int jj = 0; jj < 4; jj++) acc[i][jj] = 0.f;

    // ---- stage 1: two passes (agg@W_l, feat@W_r) accumulated ----
    for (int p = 0; p < 2; p++) {
        const float* A = p ? feat : g_agg;
        const float* W = p ? W_r : W_l;
        __syncthreads();
        for (int idx = tid; idx < 64 * 128; idx += 256) {
            int i = idx >> 7, k = idx & 127;
            int n = n0 + i;
            As[idx] = (n < N_NODES) ? A[(size_t)n * 128 + k] : 0.0f;
        }
        for (int kt = 0; kt < 8; kt++) {
            __syncthreads();
            for (int idx = tid; idx < 2048; idx += 256) {
                int t = idx >> 4, kk = idx & 15;
                Bs[kk * 132 + t] = W[t * 128 + kt * 16 + kk];
            }
            __syncthreads();
#pragma unroll
            for (int kk = 0; kk < 16; kk++) {
                float4 b = *(const float4*)&Bs[kk * 132 + c * 4];
#pragma unroll
                for (int ni = 0; ni < 8; ni++) {
                    float a = As[(rg * 8 + ni) * 128 + kt * 16 + kk];
                    acc[ni][0] += a * b.x;
                    acc[ni][1] += a * b.y;
                    acc[ni][2] += a * b.z;
                    acc[ni][3] += a * b.w;
                }
            }
        }
    }

    // ---- epilogue: relu * mask1 * mask2, store H into As (reuse) ----
    __syncthreads();
#pragma unroll
    for (int ni = 0; ni < 8; ni++) {
        int n = n0 + rg * 8 + ni;
        float4 m1 = make_float4(0.f, 0.f, 0.f, 0.f);
        float4 m2 = make_float4(0.f, 0.f, 0.f, 0.f);
        if (n < N_NODES) {
            m1 = *(const float4*)&mask1[(size_t)n * 128 + c * 4];
            m2 = *(const float4*)&mask2[(size_t)n * 128 + c * 4];
        }
        float h0 = fmaxf(acc[ni][0], 0.f) * m1.x * m2.x;
        float h1 = fmaxf(acc[ni][1], 0.f) * m1.y * m2.y;
        float h2v = fmaxf(acc[ni][2], 0.f) * m1.z * m2.z;
        float h3 = fmaxf(acc[ni][3], 0.f) * m1.w * m2.w;
        *(float4*)&As[(rg * 8 + ni) * 128 + c * 4] = make_float4(h0, h1, h2v, h3);
    }
    __syncthreads();

    // ---- stage 2: h2 = H @ W_out^T  (64 cols; 8 nodes x 2 cols / thread) --
    float acc2[8][2];
#pragma unroll
    for (int i = 0; i < 8; i++) { acc2[i][0] = 0.f; acc2[i][1] = 0.f; }

    for (int kt = 0; kt < 8; kt++) {
        __syncthreads();
        for (int idx = tid; idx < 1024; idx += 256) {
            int t = idx >> 4, kk = idx & 15;
            Bs[kk * 68 + t] = W_out[t * 128 + kt * 16 + kk];
        }
        __syncthreads();
#pragma unroll
        for (int kk = 0; kk < 16; kk++) {
            float b0 = Bs[kk * 68 + c * 2];
            float b1 = Bs[kk * 68 + c * 2 + 1];
#pragma unroll
            for (int ni = 0; ni < 8; ni++) {
                float a = As[(rg * 8 + ni) * 128 + kt * 16 + kk];
                acc2[ni][0] += a * b0;
                acc2[ni][1] += a * b1;
            }
        }
    }
#pragma unroll
    for (int ni = 0; ni < 8; ni++) {
        int n = n0 + rg * 8 + ni;
        if (n < N_NODES)
            ((float2*)g_h2)[(size_t)n * 32 + c] = make_float2(acc2[ni][0], acc2[ni][1]);
    }
}

// ---------------- 7. out[src] = sum h2[dst] (warp per src node) ------------
__global__ void k_out(float* __restrict__ out) {
    int w = (blockIdx.x * blockDim.x + threadIdx.x) >> 5;
    if (w >= N_NODES) return;
    int lane = threadIdx.x & 31;
    int beg = g_off_s[w], end = g_off_s[w + 1];
    const float2* H = (const float2*)g_h2;
    float ax = 0.f, ay = 0.f;
    int j = beg;
    for (; j + 4 <= end; j += 4) {
        int d0 = g_adj_s[j + 0];
        int d1 = g_adj_s[j + 1];
        int d2 = g_adj_s[j + 2];
        int d3 = g_adj_s[j + 3];
        float2 v0 = H[(size_t)d0 * 32 + lane];
        float2 v1 = H[(size_t)d1 * 32 + lane];
        float2 v2 = H[(size_t)d2 * 32 + lane];
        float2 v3 = H[(size_t)d3 * 32 + lane];
        ax += v0.x + v1.x + v2.x + v3.x;
        ay += v0.y + v1.y + v2.y + v3.y;
    }
    for (; j < end; j++) {
        int d0 = g_adj_s[j];
        float2 v0 = H[(size_t)d0 * 32 + lane];
        ax += v0.x; ay += v0.y;
    }
    ((float2*)out)[(size_t)w * 32 + lane] = make_float2(ax, ay);
}

// ---------------- launch ----------------------------------------------------
extern "C" void kernel_launch(void* const* d_in, const int* in_sizes, int n_in,
                              void* d_out, int out_size) {
    const float* feat = (const float*)d_in[0];
    const int* ei = (const int*)d_in[1];
    const float* W_l = (const float*)d_in[2];
    const float* W_r = (const float*)d_in[3];
    const float* W_out = (const float*)d_in[4];
    const float* mask1 = (const float*)d_in[5];
    const float* mask2 = (const float*)d_in[6];
    float* out = (float*)d_out;

    k_zero<<<256, 256>>>();
    k_count<<<(N_EDGES + 255) / 256, 256>>>(ei);
    k_scan<<<1, 1024>>>();
    k_fill<<<(N_EDGES + 255) / 256, 256>>>(ei);
    k_aggregate<<<(N_NODES * 32 + 255) / 256, 256>>>(feat);
    k_mlp<<<(N_NODES + 63) / 64, 256>>>(feat, W_l, W_r, W_out, mask1, mask2);
    k_out<<<(N_NODES * 32 + 255) / 256, 256>>>(out);
}

// round 3
// speedup vs baseline: 1.7882x; 1.7882x over previous
#include <cuda_runtime.h>
#include <cstdint>

#define N_NODES 100000
#define N_EDGES 3200000
#define FEAT 128
#define HID 128
#define NCLS 64
#define NCHUNK 98          // ceil(100000/1024)

// ---------------- scratch (device globals: no allocation allowed) ----------
__device__ int g_cnt_d[N_NODES];
__device__ int g_cnt_s[N_NODES];
__device__ int g_off_d[N_NODES + 1];
__device__ int g_off_s[N_NODES + 1];
__device__ int g_cur_d[N_NODES];
__device__ int g_cur_s[N_NODES];
__device__ int g_chk[2 * NCHUNK];
__device__ int g_adj_d[N_EDGES];   // src ids bucketed by dst
__device__ int g_adj_s[N_EDGES];   // dst ids bucketed by src
__device__ float g_agg[(size_t)N_NODES * FEAT];   // mean-aggregated features
__device__ float g_h2[(size_t)N_NODES * NCLS];    // post-W_out hidden

// ---------------- 1. zero counters ----------------------------------------
__global__ void k_zero() {
    int i = blockIdx.x * blockDim.x + threadIdx.x;
    int stride = gridDim.x * blockDim.x;
    for (; i < N_NODES; i += stride) {
        g_cnt_d[i] = 0;
        g_cnt_s[i] = 0;
    }
}

// ---------------- 2. count degrees (edge_index is INT32) -------------------
__global__ void k_count(const int* __restrict__ ei) {
    int i = blockIdx.x * blockDim.x + threadIdx.x;
    if (i >= N_EDGES) return;
    int s = ei[i];
    int d = ei[N_EDGES + i];
    atomicAdd(&g_cnt_s[s], 1);
    atomicAdd(&g_cnt_d[d], 1);
}

// ---------------- 3. parallel exclusive scan (3 phases) --------------------
// phase 1: per-chunk local exclusive scan + chunk totals
__global__ void k_scan1() {
    __shared__ int wsum[32];
    int bx = blockIdx.x;
    int sel = bx >= NCHUNK ? 1 : 0;
    int chunk = bx - sel * NCHUNK;
    const int* cnt = sel ? g_cnt_s : g_cnt_d;
    int* off = sel ? g_off_s : g_off_d;
    int tid = threadIdx.x, lane = tid & 31, wid = tid >> 5;
    int i = chunk * 1024 + tid;
    int v = (i < N_NODES) ? cnt[i] : 0;
    int x = v;
#pragma unroll
    for (int o = 1; o < 32; o <<= 1) {
        int y = __shfl_up_sync(0xffffffffu, x, o);
        if (lane >= o) x += y;
    }
    if (lane == 31) wsum[wid] = x;
    __syncthreads();
    if (wid == 0) {
        int xx = wsum[lane];
#pragma unroll
        for (int o = 1; o < 32; o <<= 1) {
            int y = __shfl_up_sync(0xffffffffu, xx, o);
            if (lane >= o) xx += y;
        }
        wsum[lane] = xx;
    }
    __syncthreads();
    int excl = x - v + (wid > 0 ? wsum[wid - 1] : 0);
    if (i < N_NODES) off[i] = excl;
    if (tid == 1023) g_chk[sel * NCHUNK + chunk] = wsum[31];
}

// phase 2: scan the chunk totals (98 per array; two 128-halves in one block)
__global__ void k_scan2() {
    __shared__ int sh[256];
    int tid = threadIdx.x;
    int sel = tid >> 7, idx = tid & 127;
    int v = (idx < NCHUNK) ? g_chk[sel * NCHUNK + idx] : 0;
    sh[tid] = v;
    __syncthreads();
#pragma unroll
    for (int o = 1; o < 128; o <<= 1) {
        int y = (idx >= o) ? sh[tid - o] : 0;
        __syncthreads();
        sh[tid] += y;
        __syncthreads();
    }
    if (idx < NCHUNK) g_chk[sel * NCHUNK + idx] = sh[tid] - v;  // exclusive
    if (tid == 0) {
        g_off_d[N_NODES] = N_EDGES;   // totals known a priori
        g_off_s[N_NODES] = N_EDGES;
    }
}

// phase 3: add chunk prefixes, init cursors
__global__ void k_scan3() {
    int bx = blockIdx.x;
    int sel = bx >= NCHUNK ? 1 : 0;
    int chunk = bx - sel * NCHUNK;
    int i = chunk * 1024 + threadIdx.x;
    if (i >= N_NODES) return;
    int add = g_chk[sel * NCHUNK + chunk];
    if (sel) {
        int p = g_off_s[i] + add;
        g_off_s[i] = p;
        g_cur_s[i] = p;
    } else {
        int p = g_off_d[i] + add;
        g_off_d[i] = p;
        g_cur_d[i] = p;
    }
}

// ---------------- 4. fill CSR buckets --------------------------------------
__global__ void k_fill(const int* __restrict__ ei) {
    int i = blockIdx.x * blockDim.x + threadIdx.x;
    if (i >= N_EDGES) return;
    int s = ei[i];
    int d = ei[N_EDGES + i];
    int p = atomicAdd(&g_cur_d[d], 1);
    g_adj_d[p] = s;
    int q = atomicAdd(&g_cur_s[s], 1);
    g_adj_s[q] = d;
}

// ---------------- 5. mean aggregation (warp per dst node, no atomics) ------
__global__ void k_aggregate(const float* __restrict__ feat) {
    int w = (blockIdx.x * blockDim.x + threadIdx.x) >> 5;
    if (w >= N_NODES) return;
    int lane = threadIdx.x & 31;
    int beg = g_off_d[w], end = g_off_d[w + 1];
    const float4* F = (const float4*)feat;
    float ax = 0.f, ay = 0.f, az = 0.f, aw = 0.f;
    int j = beg;
    for (; j + 4 <= end; j += 4) {
        int s0 = g_adj_d[j + 0];
        int s1 = g_adj_d[j + 1];
        int s2 = g_adj_d[j + 2];
        int s3 = g_adj_d[j + 3];
        float4 v0 = F[(size_t)s0 * 32 + lane];
        float4 v1 = F[(size_t)s1 * 32 + lane];
        float4 v2 = F[(size_t)s2 * 32 + lane];
        float4 v3 = F[(size_t)s3 * 32 + lane];
        ax += v0.x + v1.x + v2.x + v3.x;
        ay += v0.y + v1.y + v2.y + v3.y;
        az += v0.z + v1.z + v2.z + v3.z;
        aw += v0.w + v1.w + v2.w + v3.w;
    }
    for (; j < end; j++) {
        int s0 = g_adj_d[j];
        float4 v0 = F[(size_t)s0 * 32 + lane];
        ax += v0.x; ay += v0.y; az += v0.z; aw += v0.w;
    }
    float inv = (end > beg) ? 1.0f / (float)(end - beg) : 0.0f;
    float4 r;
    r.x = ax * inv; r.y = ay * inv; r.z = az * inv; r.w = aw * inv;
    ((float4*)g_agg)[(size_t)w * 32 + lane] = r;
}

// ---------------- 6. fused MLP on tensor cores (tf32 mma.sync) -------------
// h = relu(agg@W_l^T + feat@W_r^T) * mask1 * mask2 ; h2 = h @ W_out^T
// Block 256 thr = 8 warps, 64-node tile. Warp (rw, cw): rows rw*16..+15,
// stage1 cols cw*64..+63 (8 n-tiles), stage2 cols cw*32..+31 (4 n-tiles).
#define SA 132
#define SB 20

__device__ __forceinline__ uint32_t f2tf32(float v) {
    uint32_t u;
    asm("cvt.rna.tf32.f32 %0, %1;" : "=r"(u) : "f"(v));
    return u;
}

__device__ __forceinline__ void mma_tf32(float c[4], uint32_t a0, uint32_t a1,
                                         uint32_t a2, uint32_t a3,
                                         uint32_t b0, uint32_t b1) {
    asm volatile(
        "mma.sync.aligned.m16n8k8.row.col.f32.tf32.tf32.f32 "
        "{%0,%1,%2,%3}, {%4,%5,%6,%7}, {%8,%9}, {%0,%1,%2,%3};"
        : "+f"(c[0]), "+f"(c[1]), "+f"(c[2]), "+f"(c[3])
        : "r"(a0), "r"(a1), "r"(a2), "r"(a3), "r"(b0), "r"(b1));
}

__global__ __launch_bounds__(256) void k_mlp(
    const float* __restrict__ feat,
    const float* __restrict__ W_l, const float* __restrict__ W_r,
    const float* __restrict__ W_out,
    const float* __restrict__ mask1, const float* __restrict__ mask2) {
    __shared__ __align__(16) float As[64 * SA];    // A tile / H tile (tf32 vals)
    __shared__ __align__(16) float Bs[128 * SB];   // weight k-tile (tf32 vals)

    int tid = threadIdx.x;
    int lane = tid & 31, w = tid >> 5;
    int rw = w & 3, cw = w >> 2;
    int g = lane >> 2, t = lane & 3;
    int n0 = blockIdx.x * 64;

    float acc[8][4];
#pragma unroll
    for (int j = 0; j < 8; j++)
#pragma unroll
        for (int q = 0; q < 4; q++) acc[j][q] = 0.f;

    // ---- stage 1: two passes (agg@W_l, feat@W_r) accumulated ----
    for (int p = 0; p < 2; p++) {
        const float* A = p ? feat : g_agg;
        const float* W = p ? W_r : W_l;
        __syncthreads();
        for (int idx = tid; idx < 64 * 128; idx += 256) {
            int i = idx >> 7, k = idx & 127;
            int n = n0 + i;
            float v = (n < N_NODES) ? A[(size_t)n * 128 + k] : 0.f;
            As[i * SA + k] = __uint_as_float(f2tf32(v));
        }
        for (int kt = 0; kt < 8; kt++) {
            __syncthreads();
            for (int idx = tid; idx < 2048; idx += 256) {
                int n = idx >> 4, k = idx & 15;
                Bs[n * SB + k] = __uint_as_float(f2tf32(W[n * 128 + kt * 16 + k]));
            }
            __syncthreads();
#pragma unroll
            for (int ks = 0; ks < 2; ks++) {
                int kb = kt * 16 + ks * 8;
                int ar = rw * 16 + g;
                uint32_t a0 = __float_as_uint(As[ar * SA + kb + t]);
                uint32_t a1 = __float_as_uint(As[(ar + 8) * SA + kb + t]);
                uint32_t a2 = __float_as_uint(As[ar * SA + kb + 4 + t]);
                uint32_t a3 = __float_as_uint(As[(ar + 8) * SA + kb + 4 + t]);
#pragma unroll
                for (int j = 0; j < 8; j++) {
                    int bn = cw * 64 + j * 8 + g;
                    uint32_t b0 = __float_as_uint(Bs[bn * SB + ks * 8 + t]);
                    uint32_t b1 = __float_as_uint(Bs[bn * SB + ks * 8 + 4 + t]);
                    mma_tf32(acc[j], a0, a1, a2, a3, b0, b1);
                }
            }
        }
    }

    // ---- epilogue: relu * mask1 * mask2 -> H (tf32) into As ----
    __syncthreads();
    {
        int r0 = rw * 16 + g, r1 = r0 + 8;
        int nA = n0 + r0, nB = n0 + r1;
#pragma unroll
        for (int j = 0; j < 8; j++) {
            int col = cw * 64 + j * 8 + 2 * t;
            float2 z = make_float2(0.f, 0.f);
            float2 m1a = z, m2a = z, m1b = z, m2b = z;
            if (nA < N_NODES) {
                m1a = *(const float2*)&mask1[(size_t)nA * 128 + col];
                m2a = *(const float2*)&mask2[(size_t)nA * 128 + col];
            }
            if (nB < N_NODES) {
                m1b = *(const float2*)&mask1[(size_t)nB * 128 + col];
                m2b = *(const float2*)&mask2[(size_t)nB * 128 + col];
            }
            float h0 = fmaxf(acc[j][0], 0.f) * m1a.x * m2a.x;
            float h1 = fmaxf(acc[j][1], 0.f) * m1a.y * m2a.y;
            float h2v = fmaxf(acc[j][2], 0.f) * m1b.x * m2b.x;
            float h3 = fmaxf(acc[j][3], 0.f) * m1b.y * m2b.y;
            As[r0 * SA + col] = __uint_as_float(f2tf32(h0));
            As[r0 * SA + col + 1] = __uint_as_float(f2tf32(h1));
            As[r1 * SA + col] = __uint_as_float(f2tf32(h2v));
            As[r1 * SA + col + 1] = __uint_as_float(f2tf32(h3));
        }
    }

    // ---- stage 2: h2 = H @ W_out^T (64 out cols) ----
    float acc2[4][4];
#pragma unroll
    for (int j = 0; j < 4; j++)
#pragma unroll
        for (int q = 0; q < 4; q++) acc2[j][q] = 0.f;

    for (int kt = 0; kt < 8; kt++) {
        __syncthreads();   // also orders epilogue As writes before H reads
        for (int idx = tid; idx < 1024; idx += 256) {
            int n = idx >> 4, k = idx & 15;
            Bs[n * SB + k] = __uint_as_float(f2tf32(W_out[n * 128 + kt * 16 + k]));
        }
        __syncthreads();
#pragma unroll
        for (int ks = 0; ks < 2; ks++) {
            int kb = kt * 16 + ks * 8;
            int ar = rw * 16 + g;
            uint32_t a0 = __float_as_uint(As[ar * SA + kb + t]);
            uint32_t a1 = __float_as_uint(As[(ar + 8) * SA + kb + t]);
            uint32_t a2 = __float_as_uint(As[ar * SA + kb + 4 + t]);
            uint32_t a3 = __float_as_uint(As[(ar + 8) * SA + kb + 4 + t]);
#pragma unroll
            for (int j = 0; j < 4; j++) {
                int bn = cw * 32 + j * 8 + g;
                uint32_t b0 = __float_as_uint(Bs[bn * SB + ks * 8 + t]);
                uint32_t b1 = __float_as_uint(Bs[bn * SB + ks * 8 + 4 + t]);
                mma_tf32(acc2[j], a0, a1, a2, a3, b0, b1);
            }
        }
    }

    {
        int r0 = rw * 16 + g;
        int nA = n0 + r0, nB = nA + 8;
#pragma unroll
        for (int j = 0; j < 4; j++) {
            int col = cw * 32 + j * 8 + 2 * t;
            if (nA < N_NODES)
                *(float2*)&g_h2[(size_t)nA * 64 + col] = make_float2(acc2[j][0], acc2[j][1]);
            if (nB < N_NODES)
                *(float2*)&g_h2[(size_t)nB * 64 + col] = make_float2(acc2[j][2], acc2[j][3]);
        }
    }
}

// ---------------- 7. out[src] = sum h2[dst] (warp per src node) ------------
__global__ void k_out(float* __restrict__ out) {
    int w = (blockIdx.x * blockDim.x + threadIdx.x) >> 5;
    if (w >= N_NODES) return;
    int lane = threadIdx.x & 31;
    int beg = g_off_s[w], end = g_off_s[w + 1];
    const float2* H = (const float2*)g_h2;
    float ax = 0.f, ay = 0.f;
    int j = beg;
    for (; j + 4 <= end; j += 4) {
        int d0 = g_adj_s[j + 0];
        int d1 = g_adj_s[j + 1];
        int d2 = g_adj_s[j + 2];
        int d3 = g_adj_s[j + 3];
        float2 v0 = H[(size_t)d0 * 32 + lane];
        float2 v1 = H[(size_t)d1 * 32 + lane];
        float2 v2 = H[(size_t)d2 * 32 + lane];
        float2 v3 = H[(size_t)d3 * 32 + lane];
        ax += v0.x + v1.x + v2.x + v3.x;
        ay += v0.y + v1.y + v2.y + v3.y;
    }
    for (; j < end; j++) {
        int d0 = g_adj_s[j];
        float2 v0 = H[(size_t)d0 * 32 + lane];
        ax += v0.x; ay += v0.y;
    }
    ((float2*)out)[(size_t)w * 32 + lane] = make_float2(ax, ay);
}

// ---------------- launch ----------------------------------------------------
extern "C" void kernel_launch(void* const* d_in, const int* in_sizes, int n_in,
                              void* d_out, int out_size) {
    const float* feat = (const float*)d_in[0];
    const int* ei = (const int*)d_in[1];
    const float* W_l = (const float*)d_in[2];
    const float* W_r = (const float*)d_in[3];
    const float* W_out = (const float*)d_in[4];
    const float* mask1 = (const float*)d_in[5];
    const float* mask2 = (const float*)d_in[6];
    float* out = (float*)d_out;

    k_zero<<<256, 256>>>();
    k_count<<<(N_EDGES + 255) / 256, 256>>>(ei);
    k_scan1<<<2 * NCHUNK, 1024>>>();
    k_scan2<<<1, 256>>>();
    k_scan3<<<2 * NCHUNK, 1024>>>();
    k_fill<<<(N_EDGES + 255) / 256, 256>>>(ei);
    k_aggregate<<<(N_NODES * 32 + 255) / 256, 256>>>(feat);
    k_mlp<<<(N_NODES + 63) / 64, 256>>>(feat, W_l, W_r, W_out, mask1, mask2);
    k_out<<<(N_NODES * 32 + 255) / 256, 256>>>(out);
}